// round 6
// baseline (speedup 1.0000x reference)
#include <cuda_runtime.h>
#include <cuda_bf16.h>
#include <cstdint>
#include <math.h>

// Problem constants
#define BB 2
#define SS 2048
#define EE 2048
#define HH 16
#define DD 128
#define MM (BB*SS)   // 4096

// ---------------------------------------------------------------------------
// Scratch (alloc-free: __device__ globals)
// ---------------------------------------------------------------------------
__device__ float g_Q[(size_t)MM * EE];   // Q projection (fp32)
__device__ float g_K[(size_t)MM * DD];
__device__ float g_V[(size_t)MM * DD];
__device__ float g_C[(size_t)MM * EE];   // attention out (fp32)

// ---------------------------------------------------------------------------
// Base-target-safe PTX helpers (cp.async, mma.sync, ldmatrix, cvt.tf32)
// ---------------------------------------------------------------------------
__device__ __forceinline__ uint32_t smem_u32(const void* p) {
    uint32_t a;
    asm("{ .reg .u64 t; cvta.to.shared.u64 t, %1; cvt.u32.u64 %0, t; }"
        : "=r"(a) : "l"(p));
    return a;
}

#define CP_ASYNC16(dst, src) \
    asm volatile("cp.async.cg.shared.global [%0], [%1], 16;" \
                 :: "r"(dst), "l"(src) : "memory")
#define CP_COMMIT() asm volatile("cp.async.commit_group;" ::: "memory")
#define CP_WAIT(n)  asm volatile("cp.async.wait_group %0;" :: "n"(n) : "memory")

#define LDSM_X4(r0, r1, r2, r3, addr) \
    asm volatile("ldmatrix.sync.aligned.m8n8.x4.shared.b16 {%0,%1,%2,%3}, [%4];" \
                 : "=r"(r0), "=r"(r1), "=r"(r2), "=r"(r3) : "r"(addr))

__device__ __forceinline__ float tf32r(float x) {
    uint32_t u;
    asm("cvt.rna.tf32.f32 %0, %1;" : "=r"(u) : "f"(x));
    return __uint_as_float(u);
}
__device__ __forceinline__ float4 tf32r4(float4 v) {
    v.x = tf32r(v.x); v.y = tf32r(v.y); v.z = tf32r(v.z); v.w = tf32r(v.w);
    return v;
}
// tf32-round a raw fp32 bit pattern (for post-ldmatrix rounding)
__device__ __forceinline__ uint32_t cvtb(uint32_t b) {
    uint32_t o;
    asm("cvt.rna.tf32.f32 %0, %1;" : "=r"(o) : "f"(__uint_as_float(b)));
    return o;
}
__device__ __forceinline__ uint32_t fbits(float x) { return __float_as_uint(x); }

// m16n8k8 tf32 MMA, fp32 accum, D==C in-place
__device__ __forceinline__ void mma_tf32(float d[4], const uint32_t a[4],
                                         const uint32_t b[2]) {
    asm volatile(
        "mma.sync.aligned.m16n8k8.row.col.f32.tf32.tf32.f32 "
        "{%0,%1,%2,%3}, {%4,%5,%6,%7}, {%8,%9}, {%0,%1,%2,%3};"
        : "+f"(d[0]), "+f"(d[1]), "+f"(d[2]), "+f"(d[3])
        : "r"(a[0]), "r"(a[1]), "r"(a[2]), "r"(a[3]),
          "r"(b[0]), "r"(b[1]));
}

// ---------------------------------------------------------------------------
// Tensor-core tf32 GEMM: C[M,N] = A[M,K] @ B[N,K]^T + bias[N]
// Raw fp32 inputs; tf32 rounding applied in-register after ldmatrix.
// CTA tile 128x128x32, 8 warps (2m x 4n). 4-stage cp.async pipeline.
// smem rows 36 floats (144B: 16B-aligned, stride=9 chunks => conflict-free).
// ---------------------------------------------------------------------------
#define GBK 32
#define GROW 36
#define GTILE (128*GROW)
#define GSTAGE (2*GTILE)
#define GSTAGES 4
#define SMEM_GEMM (GSTAGES*GSTAGE*4)    // 147456 bytes

__global__ void __launch_bounds__(256)
gemm_mma_tf32(const float* __restrict__ A, const float* __restrict__ Bw,
              const float* __restrict__ bias, float* __restrict__ C,
              int M, int N, int K)
{
    extern __shared__ __align__(16) float sg[];
    const uint32_t smem_base = smem_u32(sg);
    const int tid = threadIdx.x;
    const int wid = tid >> 5, lane = tid & 31;
    const int g = lane >> 2, t = lane & 3;
    const int wm = wid >> 2, wn = wid & 3;
    const int m0 = blockIdx.y * 128, n0 = blockIdx.x * 128;
    const int m0w = wm * 64, n0w = wn * 32;

    const char* Ab = (const char*)(A  + (size_t)m0 * K);
    const char* Bb = (const char*)(Bw + (size_t)n0 * K);
    const size_t rowKB = (size_t)K * 4;
    const int NK = K / GBK;

    auto stage_load = [&](int kt, int buf) {
        uint32_t sA = smem_base + (uint32_t)(buf*GSTAGE)*4;
        uint32_t sB = sA + GTILE*4;
        const char* gA = Ab + (size_t)kt * (GBK*4);
        const char* gB = Bb + (size_t)kt * (GBK*4);
#pragma unroll
        for (int i = 0; i < 4; i++) {
            int c   = tid + i*256;
            int row = c >> 3;
            int ch  = c & 7;
            uint32_t d = (uint32_t)row*(GROW*4) + (uint32_t)ch*16;
            CP_ASYNC16(sA + d, gA + (size_t)row*rowKB + ch*16);
            CP_ASYNC16(sB + d, gB + (size_t)row*rowKB + ch*16);
        }
    };

    stage_load(0, 0); CP_COMMIT();
    stage_load(1, 1); CP_COMMIT();
    stage_load(2, 2); CP_COMMIT();

    // ldmatrix per-lane offsets (bytes)
    const uint32_t laneA = (uint32_t)(((lane & 7) + ((lane >> 3) & 1)*8)*(GROW*4)
                                      + ((lane >> 4) & 1)*16);
    const uint32_t laneB = (uint32_t)(((lane & 7) + ((lane >> 4) & 1)*8)*(GROW*4)
                                      + ((lane >> 3) & 1)*16);

    float acc[4][4][4];
#pragma unroll
    for (int mf = 0; mf < 4; mf++)
#pragma unroll
        for (int nf = 0; nf < 4; nf++)
#pragma unroll
            for (int r = 0; r < 4; r++) acc[mf][nf][r] = 0.f;

    for (int kt = 0; kt < NK; kt++) {
        CP_WAIT(2);
        __syncthreads();
        if (kt + 3 < NK) stage_load(kt + 3, (kt + 3) % GSTAGES);
        CP_COMMIT();

        const uint32_t As = smem_base + (uint32_t)((kt % GSTAGES)*GSTAGE)*4;
        const uint32_t Bs = As + GTILE*4;
        const uint32_t Aw = As + (uint32_t)(m0w*GROW)*4 + laneA;
        const uint32_t Bw2 = Bs + (uint32_t)(n0w*GROW)*4 + laneB;

#pragma unroll
        for (int k8 = 0; k8 < GBK/8; k8++) {
            const uint32_t kb = k8*32;
            uint32_t a[4][4];
#pragma unroll
            for (int mf = 0; mf < 4; mf++) {
                LDSM_X4(a[mf][0], a[mf][1], a[mf][2], a[mf][3],
                        Aw + (uint32_t)(mf*16*GROW)*4 + kb);
                a[mf][0] = cvtb(a[mf][0]); a[mf][1] = cvtb(a[mf][1]);
                a[mf][2] = cvtb(a[mf][2]); a[mf][3] = cvtb(a[mf][3]);
            }
            uint32_t b[2][4];
#pragma unroll
            for (int p = 0; p < 2; p++) {
                LDSM_X4(b[p][0], b[p][1], b[p][2], b[p][3],
                        Bw2 + (uint32_t)(p*16*GROW)*4 + kb);
                b[p][0] = cvtb(b[p][0]); b[p][1] = cvtb(b[p][1]);
                b[p][2] = cvtb(b[p][2]); b[p][3] = cvtb(b[p][3]);
            }
#pragma unroll
            for (int mf = 0; mf < 4; mf++)
#pragma unroll
                for (int p = 0; p < 2; p++) {
                    mma_tf32(acc[mf][2*p+0], a[mf], &b[p][0]);
                    mma_tf32(acc[mf][2*p+1], a[mf], &b[p][2]);
                }
        }
    }

    // epilogue: bias add + store
#pragma unroll
    for (int mf = 0; mf < 4; mf++) {
        const int r0 = m0 + m0w + mf*16 + g;
#pragma unroll
        for (int nf = 0; nf < 4; nf++) {
            const int col = n0 + n0w + nf*8 + t*2;
            float2 bb = *reinterpret_cast<const float2*>(bias + col);
            float2 v0 = { acc[mf][nf][0] + bb.x, acc[mf][nf][1] + bb.y };
            float2 v1 = { acc[mf][nf][2] + bb.x, acc[mf][nf][3] + bb.y };
            *reinterpret_cast<float2*>(C + (size_t)r0*N + col)     = v0;
            *reinterpret_cast<float2*>(C + (size_t)(r0+8)*N + col) = v1;
        }
    }
}

// ---------------------------------------------------------------------------
// Tensor-core causal MQA flash attention (tf32 mma, fp32 softmax/accum)
// Br=128 (8 warps x m16), Bc=32 keys/tile, D=128. grid (S/128, H, B), blk 256.
// Q staged once -> registers; smem region reused for K / V^T / P.
//   Qstage: [128][132]  (67584 B, prologue only)
//   Ks [32][132] | Vt [128][36] | Ps [8][16][36]   (reuse, 53760 B)
// ---------------------------------------------------------------------------
#define AQROW 132
#define AVROW 36
#define SMEM_ATTN (128*AQROW*4)   // 67584

__global__ void __launch_bounds__(256)
mqa_attn_tc(const float* __restrict__ Q, const float* __restrict__ Kb,
            const float* __restrict__ Vb, float* __restrict__ O)
{
    extern __shared__ __align__(16) float sa[];
    const uint32_t smem_base = smem_u32(sa);
    float* Ks = sa;                      // [32][132]
    float* Vt = sa + 32*AQROW;           // [128][36], row=d, col=key
    float* Ps = Vt + 128*AVROW;          // [8][16][36]

    const int qt = blockIdx.x, h = blockIdx.y, b = blockIdx.z;
    const int q0 = qt * 128;
    const int tid = threadIdx.x;
    const int w = tid >> 5, lane = tid & 31;
    const int g = lane >> 2, t = lane & 3;
    float* Pw = Ps + w*16*AVROW;
    const uint32_t PwA = smem_base + (uint32_t)((32*AQROW + 128*AVROW
                                                 + w*16*AVROW))*4;
    const uint32_t KsA = smem_base;
    const uint32_t VtA = smem_base + (uint32_t)(32*AQROW)*4;

    const float scale = 0.08838834764831845f;   // 1/sqrt(128)
    const float* Qp = Q  + ((size_t)(b*SS + q0))*EE + h*DD;
    const float* Kp = Kb + (size_t)b*SS*DD;
    const float* Vp = Vb + (size_t)b*SS*DD;

    // per-lane ldmatrix offsets
    const uint32_t laneAQ = (uint32_t)(((lane & 7) + ((lane >> 3) & 1)*8)*(AQROW*4)
                                       + ((lane >> 4) & 1)*16);
    const uint32_t laneBK = (uint32_t)(((lane & 7) + ((lane >> 4) & 1)*8)*(AQROW*4)
                                       + ((lane >> 3) & 1)*16);
    const uint32_t laneAP = (uint32_t)(((lane & 7) + ((lane >> 3) & 1)*8)*(AVROW*4)
                                       + ((lane >> 4) & 1)*16);
    const uint32_t laneBV = (uint32_t)(((lane & 7) + ((lane >> 4) & 1)*8)*(AVROW*4)
                                       + ((lane >> 3) & 1)*16);

    // ---- prologue: stage Q (scaled + tf32-rounded), move to registers ----
    for (int i = tid; i < 128*32; i += 256) {
        int r = i >> 5, c4 = (i & 31)*4;
        float4 v = *reinterpret_cast<const float4*>(Qp + (size_t)r*EE + c4);
        v.x = tf32r(v.x*scale); v.y = tf32r(v.y*scale);
        v.z = tf32r(v.z*scale); v.w = tf32r(v.w*scale);
        *reinterpret_cast<float4*>(sa + r*AQROW + c4) = v;
    }
    __syncthreads();

    uint32_t qa[16][4];
    {
        const uint32_t Qw = smem_base + (uint32_t)(w*16*AQROW)*4 + laneAQ;
#pragma unroll
        for (int k8 = 0; k8 < 16; k8++)
            LDSM_X4(qa[k8][0], qa[k8][1], qa[k8][2], qa[k8][3], Qw + k8*32);
    }

    float o[16][4];
#pragma unroll
    for (int df = 0; df < 16; df++)
#pragma unroll
        for (int r = 0; r < 4; r++) o[df][r] = 0.f;
    float m0r = -1e30f, m1r = -1e30f, l0r = 0.f, l1r = 0.f;

    const int nk = 4*(qt + 1);
    for (int kt = 0; kt < nk; kt++) {
        const int k0 = kt * 32;
        __syncthreads();   // Qstage free (1st iter) / prior PV reads done

        // K tile [32 keys][128 d] row-major, tf32-rounded
        for (int i = tid; i < 32*32; i += 256) {
            int r = i >> 5, c4 = (i & 31)*4;
            float4 v = tf32r4(*reinterpret_cast<const float4*>(
                              Kp + (size_t)(k0+r)*DD + c4));
            *reinterpret_cast<float4*>(Ks + r*AQROW + c4) = v;
        }
        // V tile transposed: Vt[d][key], lanes = keys (conflict-free STS)
        for (int i = tid; i < 32*32; i += 256) {
            int r = i & 31, ch = i >> 5;
            float4 v = tf32r4(*reinterpret_cast<const float4*>(
                              Vp + (size_t)(k0+r)*DD + ch*4));
            Vt[(ch*4+0)*AVROW + r] = v.x;
            Vt[(ch*4+1)*AVROW + r] = v.y;
            Vt[(ch*4+2)*AVROW + r] = v.z;
            Vt[(ch*4+3)*AVROW + r] = v.w;
        }
        __syncthreads();

        // ---- S = Q K^T ----
        float s[4][4];
#pragma unroll
        for (int nf = 0; nf < 4; nf++)
#pragma unroll
            for (int r = 0; r < 4; r++) s[nf][r] = 0.f;

#pragma unroll
        for (int k8 = 0; k8 < 16; k8++) {
            const uint32_t kb = k8*32;
            uint32_t kf[2][4];
#pragma unroll
            for (int p = 0; p < 2; p++)
                LDSM_X4(kf[p][0], kf[p][1], kf[p][2], kf[p][3],
                        KsA + (uint32_t)(p*16*AQROW)*4 + kb + laneBK);
#pragma unroll
            for (int p = 0; p < 2; p++) {
                mma_tf32(s[2*p+0], qa[k8], &kf[p][0]);
                mma_tf32(s[2*p+1], qa[k8], &kf[p][2]);
            }
        }

        // ---- causal mask ----
        if (k0 + 31 > q0 + w*16) {
            const int r0 = q0 + w*16 + g, r1 = r0 + 8;
#pragma unroll
            for (int nf = 0; nf < 4; nf++) {
                const int c0 = k0 + nf*8 + t*2, c1 = c0 + 1;
                if (c0 > r0) s[nf][0] = -1e30f;
                if (c1 > r0) s[nf][1] = -1e30f;
                if (c0 > r1) s[nf][2] = -1e30f;
                if (c1 > r1) s[nf][3] = -1e30f;
            }
        }

        // ---- online softmax: row g ----
        {
            float mt = fmaxf(fmaxf(s[0][0], s[0][1]), fmaxf(s[1][0], s[1][1]));
            mt = fmaxf(mt, fmaxf(fmaxf(s[2][0], s[2][1]), fmaxf(s[3][0], s[3][1])));
            mt = fmaxf(mt, __shfl_xor_sync(0xffffffffu, mt, 1));
            mt = fmaxf(mt, __shfl_xor_sync(0xffffffffu, mt, 2));
            float mn = fmaxf(m0r, mt);
            float corr = __expf(m0r - mn);
            m0r = mn;
            float ps = 0.f;
#pragma unroll
            for (int nf = 0; nf < 4; nf++) {
                s[nf][0] = __expf(s[nf][0] - mn); ps += s[nf][0];
                s[nf][1] = __expf(s[nf][1] - mn); ps += s[nf][1];
            }
            ps += __shfl_xor_sync(0xffffffffu, ps, 1);
            ps += __shfl_xor_sync(0xffffffffu, ps, 2);
            l0r = l0r*corr + ps;
#pragma unroll
            for (int df = 0; df < 16; df++) { o[df][0] *= corr; o[df][1] *= corr; }
#pragma unroll
            for (int nf = 0; nf < 4; nf++) {
                float2 p = { tf32r(s[nf][0]), tf32r(s[nf][1]) };
                *reinterpret_cast<float2*>(Pw + g*AVROW + nf*8 + t*2) = p;
            }
        }
        // ---- row g+8 ----
        {
            float mt = fmaxf(fmaxf(s[0][2], s[0][3]), fmaxf(s[1][2], s[1][3]));
            mt = fmaxf(mt, fmaxf(fmaxf(s[2][2], s[2][3]), fmaxf(s[3][2], s[3][3])));
            mt = fmaxf(mt, __shfl_xor_sync(0xffffffffu, mt, 1));
            mt = fmaxf(mt, __shfl_xor_sync(0xffffffffu, mt, 2));
            float mn = fmaxf(m1r, mt);
            float corr = __expf(m1r - mn);
            m1r = mn;
            float ps = 0.f;
#pragma unroll
            for (int nf = 0; nf < 4; nf++) {
                s[nf][2] = __expf(s[nf][2] - mn); ps += s[nf][2];
                s[nf][3] = __expf(s[nf][3] - mn); ps += s[nf][3];
            }
            ps += __shfl_xor_sync(0xffffffffu, ps, 1);
            ps += __shfl_xor_sync(0xffffffffu, ps, 2);
            l1r = l1r*corr + ps;
#pragma unroll
            for (int df = 0; df < 16; df++) { o[df][2] *= corr; o[df][3] *= corr; }
#pragma unroll
            for (int nf = 0; nf < 4; nf++) {
                float2 p = { tf32r(s[nf][2]), tf32r(s[nf][3]) };
                *reinterpret_cast<float2*>(Pw + (g+8)*AVROW + nf*8 + t*2) = p;
            }
        }
        __syncwarp();   // Ps is warp-private

        // ---- O += P V ----
#pragma unroll
        for (int j8 = 0; j8 < 4; j8++) {
            const uint32_t jb = j8*32;
            uint32_t pa[4];
            LDSM_X4(pa[0], pa[1], pa[2], pa[3], PwA + jb + laneAP);
#pragma unroll
            for (int dp = 0; dp < 8; dp++) {
                uint32_t vb[4];
                LDSM_X4(vb[0], vb[1], vb[2], vb[3],
                        VtA + (uint32_t)(dp*16*AVROW)*4 + jb + laneBV);
                mma_tf32(o[2*dp+0], pa, &vb[0]);
                mma_tf32(o[2*dp+1], pa, &vb[2]);
            }
        }
    }

    // normalize + store (raw fp32; O-proj rounds in-register)
    const float inv0 = 1.f / l0r, inv1 = 1.f / l1r;
    float* Op = O + ((size_t)(b*SS + q0 + w*16))*EE + h*DD;
#pragma unroll
    for (int df = 0; df < 16; df++) {
        const int col = df*8 + t*2;
        float2 v0 = { o[df][0]*inv0, o[df][1]*inv0 };
        float2 v1 = { o[df][2]*inv1, o[df][3]*inv1 };
        *reinterpret_cast<float2*>(Op + (size_t)(g    )*EE + col) = v0;
        *reinterpret_cast<float2*>(Op + (size_t)(g + 8)*EE + col) = v1;
    }
}

// ---------------------------------------------------------------------------
// kernel_launch
// ---------------------------------------------------------------------------
extern "C" void kernel_launch(void* const* d_in, const int* in_sizes, int n_in,
                              void* d_out, int out_size)
{
    const float* input = (const float*)d_in[0];
    const float* kv    = (const float*)d_in[1];
    const float* Wq    = (const float*)d_in[2];
    const float* bq    = (const float*)d_in[3];
    const float* Wk    = (const float*)d_in[4];
    const float* bk    = (const float*)d_in[5];
    const float* Wv    = (const float*)d_in[6];
    const float* bv    = (const float*)d_in[7];
    const float* Wo    = (const float*)d_in[8];
    const float* bo    = (const float*)d_in[9];
    float* out = (float*)d_out;

    float *gq, *gk, *gv, *gc;
    cudaGetSymbolAddress((void**)&gq, g_Q);
    cudaGetSymbolAddress((void**)&gk, g_K);
    cudaGetSymbolAddress((void**)&gv, g_V);
    cudaGetSymbolAddress((void**)&gc, g_C);

    cudaFuncSetAttribute(gemm_mma_tf32,
                         cudaFuncAttributeMaxDynamicSharedMemorySize, SMEM_GEMM);
    cudaFuncSetAttribute(mqa_attn_tc,
                         cudaFuncAttributeMaxDynamicSharedMemorySize, SMEM_ATTN);

    // projections (tensor cores, in-register tf32 rounding)
    {
        dim3 gqg(EE/128, MM/128);
        gemm_mma_tf32<<<gqg, 256, SMEM_GEMM>>>(input, Wq, bq, gq, MM, EE, EE);
        dim3 gkvg(DD/128, MM/128);
        gemm_mma_tf32<<<gkvg, 256, SMEM_GEMM>>>(kv, Wk, bk, gk, MM, DD, EE);
        gemm_mma_tf32<<<gkvg, 256, SMEM_GEMM>>>(kv, Wv, bv, gv, MM, DD, EE);
    }

    // attention (tensor cores)
    {
        dim3 grid(SS/128, HH, BB);
        mqa_attn_tc<<<grid, 256, SMEM_ATTN>>>(gq, gk, gv, gc);
    }

    // output projection into d_out
    {
        dim3 gog(EE/128, MM/128);
        gemm_mma_tf32<<<gog, 256, SMEM_GEMM>>>(gc, Wo, bo, out, MM, EE, EE);
    }
}

// round 8
// speedup vs baseline: 1.4844x; 1.4844x over previous
#include <cuda_runtime.h>
#include <cuda_bf16.h>
#include <cstdint>
#include <math.h>

// Problem constants
#define BB 2
#define SS 2048
#define EE 2048
#define HH 16
#define DD 128
#define MM (BB*SS)   // 4096

#define ATT_SCALE 0.08838834764831845f   // 1/sqrt(128)

// ---------------------------------------------------------------------------
// Scratch (alloc-free: __device__ globals)
// ---------------------------------------------------------------------------
__device__ float g_Q[(size_t)MM * EE];   // Q proj, pre-scaled + tf32-rounded
__device__ float g_K[(size_t)MM * DD];   // tf32-rounded
__device__ float g_V[(size_t)MM * DD];   // tf32-rounded
__device__ float g_C[(size_t)MM * EE];   // attention out (fp32)

// ---------------------------------------------------------------------------
// Base-target-safe PTX helpers
// ---------------------------------------------------------------------------
__device__ __forceinline__ uint32_t smem_u32(const void* p) {
    uint32_t a;
    asm("{ .reg .u64 t; cvta.to.shared.u64 t, %1; cvt.u32.u64 %0, t; }"
        : "=r"(a) : "l"(p));
    return a;
}

#define CP_ASYNC16(dst, src) \
    asm volatile("cp.async.cg.shared.global [%0], [%1], 16;" \
                 :: "r"(dst), "l"(src) : "memory")
#define CP_COMMIT() asm volatile("cp.async.commit_group;" ::: "memory")
#define CP_WAIT(n)  asm volatile("cp.async.wait_group %0;" :: "n"(n) : "memory")

#define LDSM_X4(r0, r1, r2, r3, addr) \
    asm volatile("ldmatrix.sync.aligned.m8n8.x4.shared.b16 {%0,%1,%2,%3}, [%4];" \
                 : "=r"(r0), "=r"(r1), "=r"(r2), "=r"(r3) : "r"(addr))

__device__ __forceinline__ float tf32r(float x) {
    uint32_t u;
    asm("cvt.rna.tf32.f32 %0, %1;" : "=r"(u) : "f"(x));
    return __uint_as_float(u);
}
__device__ __forceinline__ uint32_t cvtb(uint32_t b) {
    uint32_t o;
    asm("cvt.rna.tf32.f32 %0, %1;" : "=r"(o) : "f"(__uint_as_float(b)));
    return o;
}

__device__ __forceinline__ void mma_tf32(float d[4], const uint32_t a[4],
                                         const uint32_t b[2]) {
    asm volatile(
        "mma.sync.aligned.m16n8k8.row.col.f32.tf32.tf32.f32 "
        "{%0,%1,%2,%3}, {%4,%5,%6,%7}, {%8,%9}, {%0,%1,%2,%3};"
        : "+f"(d[0]), "+f"(d[1]), "+f"(d[2]), "+f"(d[3])
        : "r"(a[0]), "r"(a[1]), "r"(a[2]), "r"(a[3]),
          "r"(b[0]), "r"(b[1]));
}

// ---------------------------------------------------------------------------
// GEMM body: C[M,N] = A[M,K] @ B[N,K]^T + bias[N]   (tile BM x 128 x 32)
// BM = 32*MFRAG. 8 warps (2m x 4n). 3-stage cp.async. LDSM + in-reg tf32.
// ROUND: epilogue stores tf32r((acc+bias)*scale), else acc+bias.
// ---------------------------------------------------------------------------
#define GROW 36

template<int MFRAG, bool ROUND>
__device__ __forceinline__ void gemm_body(
    const float* __restrict__ A, const float* __restrict__ Bw,
    const float* __restrict__ bias, float* __restrict__ C,
    int M, int N, int K, float scale, int m0, int n0, float* sg)
{
    constexpr int BM     = 32*MFRAG;
    constexpr int TILE_A = BM*GROW;
    constexpr int TILE_B = 128*GROW;
    constexpr int STAGE  = TILE_A + TILE_B;

    const uint32_t smem_base = smem_u32(sg);
    const int tid = threadIdx.x;
    const int wid = tid >> 5, lane = tid & 31;
    const int g = lane >> 2, t = lane & 3;
    const int wm = wid >> 2, wn = wid & 3;
    const int m0w = wm * 16 * MFRAG, n0w = wn * 32;

    const char* Ab = (const char*)(A  + (size_t)m0 * K);
    const char* Bb = (const char*)(Bw + (size_t)n0 * K);
    const size_t rowKB = (size_t)K * 4;
    const int NK = K / 32;

    auto stage_load = [&](int kt, int buf) {
        uint32_t sA = smem_base + (uint32_t)(buf*STAGE)*4;
        uint32_t sB = sA + TILE_A*4;
        const char* gA = Ab + (size_t)kt * 128;
        const char* gB = Bb + (size_t)kt * 128;
#pragma unroll
        for (int i = 0; i < MFRAG; i++) {
            int c = tid + i*256;
            int row = c >> 3, ch = c & 7;
            CP_ASYNC16(sA + (uint32_t)row*(GROW*4) + ch*16,
                       gA + (size_t)row*rowKB + ch*16);
        }
#pragma unroll
        for (int i = 0; i < 4; i++) {
            int c = tid + i*256;
            int row = c >> 3, ch = c & 7;
            CP_ASYNC16(sB + (uint32_t)row*(GROW*4) + ch*16,
                       gB + (size_t)row*rowKB + ch*16);
        }
    };

    stage_load(0, 0); CP_COMMIT();
    stage_load(1, 1); CP_COMMIT();

    const uint32_t laneA = ((lane & 7) + ((lane >> 3) & 1)*8)*(GROW*4)
                         + ((lane >> 4) & 1)*16;
    const uint32_t laneB = ((lane & 7) + ((lane >> 4) & 1)*8)*(GROW*4)
                         + ((lane >> 3) & 1)*16;

    float acc[MFRAG][4][4];
#pragma unroll
    for (int mf = 0; mf < MFRAG; mf++)
#pragma unroll
        for (int nf = 0; nf < 4; nf++)
#pragma unroll
            for (int r = 0; r < 4; r++) acc[mf][nf][r] = 0.f;

    for (int kt = 0; kt < NK; kt++) {
        CP_WAIT(1);
        __syncthreads();
        if (kt + 2 < NK) stage_load(kt + 2, (kt + 2) % 3);
        CP_COMMIT();

        const uint32_t As = smem_base + (uint32_t)((kt % 3)*STAGE)*4;
        const uint32_t Bs = As + TILE_A*4;
        const uint32_t Aw = As + (uint32_t)(m0w*GROW)*4 + laneA;
        const uint32_t Bw2 = Bs + (uint32_t)(n0w*GROW)*4 + laneB;

#pragma unroll
        for (int k8 = 0; k8 < 4; k8++) {
            const uint32_t kb = k8*32;
            uint32_t a[MFRAG][4];
#pragma unroll
            for (int mf = 0; mf < MFRAG; mf++) {
                LDSM_X4(a[mf][0], a[mf][1], a[mf][2], a[mf][3],
                        Aw + (uint32_t)(mf*16*GROW)*4 + kb);
                a[mf][0] = cvtb(a[mf][0]); a[mf][1] = cvtb(a[mf][1]);
                a[mf][2] = cvtb(a[mf][2]); a[mf][3] = cvtb(a[mf][3]);
            }
            uint32_t b[2][4];
#pragma unroll
            for (int p = 0; p < 2; p++) {
                LDSM_X4(b[p][0], b[p][1], b[p][2], b[p][3],
                        Bw2 + (uint32_t)(p*16*GROW)*4 + kb);
                b[p][0] = cvtb(b[p][0]); b[p][1] = cvtb(b[p][1]);
                b[p][2] = cvtb(b[p][2]); b[p][3] = cvtb(b[p][3]);
            }
#pragma unroll
            for (int mf = 0; mf < MFRAG; mf++)
#pragma unroll
                for (int p = 0; p < 2; p++) {
                    mma_tf32(acc[mf][2*p+0], a[mf], &b[p][0]);
                    mma_tf32(acc[mf][2*p+1], a[mf], &b[p][2]);
                }
        }
    }

#pragma unroll
    for (int mf = 0; mf < MFRAG; mf++) {
        const int r0 = m0 + m0w + mf*16 + g;
#pragma unroll
        for (int nf = 0; nf < 4; nf++) {
            const int col = n0 + n0w + nf*8 + t*2;
            float2 bb = *reinterpret_cast<const float2*>(bias + col);
            float2 v0, v1;
            if (ROUND) {
                v0.x = tf32r((acc[mf][nf][0] + bb.x)*scale);
                v0.y = tf32r((acc[mf][nf][1] + bb.y)*scale);
                v1.x = tf32r((acc[mf][nf][2] + bb.x)*scale);
                v1.y = tf32r((acc[mf][nf][3] + bb.y)*scale);
            } else {
                v0.x = acc[mf][nf][0] + bb.x; v0.y = acc[mf][nf][1] + bb.y;
                v1.x = acc[mf][nf][2] + bb.x; v1.y = acc[mf][nf][3] + bb.y;
            }
            *reinterpret_cast<float2*>(C + (size_t)r0*N + col)     = v0;
            *reinterpret_cast<float2*>(C + (size_t)(r0+8)*N + col) = v1;
        }
    }
}

#define SMEM_G4 (3*(128+128)*GROW*4)   // 110592
#define SMEM_G2 (3*(64+128)*GROW*4)    //  82944

__global__ void __launch_bounds__(256, 2)
gemm_round(const float* __restrict__ A, const float* __restrict__ Bw,
           const float* __restrict__ bias, float* __restrict__ C,
           int M, int N, int K, float scale)
{
    extern __shared__ float sg[];
    gemm_body<4, true>(A, Bw, bias, C, M, N, K, scale,
                       blockIdx.y*128, blockIdx.x*128, sg);
}

__global__ void __launch_bounds__(256, 2)
gemm_plain(const float* __restrict__ A, const float* __restrict__ Bw,
           const float* __restrict__ bias, float* __restrict__ C,
           int M, int N, int K)
{
    extern __shared__ float sg[];
    gemm_body<4, false>(A, Bw, bias, C, M, N, K, 1.f,
                        blockIdx.y*128, blockIdx.x*128, sg);
}

// fused K+V projection: grid (2, M/64); blockIdx.x selects K or V
__global__ void __launch_bounds__(256, 2)
gemm_kv(const float* __restrict__ kvIn,
        const float* __restrict__ Wk, const float* __restrict__ bk,
        float* __restrict__ gK,
        const float* __restrict__ Wv, const float* __restrict__ bv,
        float* __restrict__ gV)
{
    extern __shared__ float sg[];
    const bool isV = (blockIdx.x != 0);
    gemm_body<2, true>(kvIn, isV ? Wv : Wk, isV ? bv : bk, isV ? gV : gK,
                       MM, DD, EE, 1.f, blockIdx.y*64, 0, sg);
}

// ---------------------------------------------------------------------------
// Tensor-core causal MQA flash attention
// Br=128 (8 warps x m16), Bc=64. grid (S/128, H, B), block 256.
// Q/K/V pre-tf32-rounded (Q pre-scaled). Pipelined: K via cp.async,
// V via register prefetch -> double-buffered transposed smem.
// smem (floats): Ks[64][132] | Vt[2][128][68] | P[8][16][68]  (Q overlays Ks..)
// ---------------------------------------------------------------------------
#define BC 64
#define KROW 132
#define VROW 68
#define OFF_V (64*KROW)                     // 8448
#define OFF_P (OFF_V + 2*128*VROW)          // 25856
#define SMEM_ATTN ((OFF_P + 8*16*VROW)*4)   // 138240

__global__ void __launch_bounds__(256)
mqa_attn_tc(const float* __restrict__ Q, const float* __restrict__ Kb,
            const float* __restrict__ Vb, float* __restrict__ O)
{
    extern __shared__ __align__(16) float sa[];
    const uint32_t base = smem_u32(sa);

    const int qt = (int)gridDim.x - 1 - (int)blockIdx.x;  // longest first
    const int h = blockIdx.y, b = blockIdx.z;
    const int q0 = qt * 128;
    const int tid = threadIdx.x;
    const int w = tid >> 5, lane = tid & 31;
    const int g = lane >> 2, t = lane & 3;
    const int vkey = tid & 63, vdg = tid >> 6;

    const float* Qp = Q  + ((size_t)(b*SS + q0))*EE + h*DD;
    const float* Kp = Kb + (size_t)b*SS*DD;
    const float* Vp = Vb + (size_t)b*SS*DD;

    const uint32_t laneAQ = ((lane&7) + ((lane>>3)&1)*8)*(KROW*4) + ((lane>>4)&1)*16;
    const uint32_t laneBK = ((lane&7) + ((lane>>4)&1)*8)*(KROW*4) + ((lane>>3)&1)*16;
    const uint32_t laneAP = ((lane&7) + ((lane>>3)&1)*8)*(VROW*4) + ((lane>>4)&1)*16;
    const uint32_t laneBV = ((lane&7) + ((lane>>4)&1)*8)*(VROW*4) + ((lane>>3)&1)*16;

    // ---- prologue: Q tile via cp.async into overlay -> registers ----
#pragma unroll
    for (int i = 0; i < 16; i++) {
        int idx = tid + i*256;
        int r = idx >> 5, ch = idx & 31;
        CP_ASYNC16(base + (uint32_t)(r*(KROW*4) + ch*16),
                   (const char*)(Qp + (size_t)r*EE) + ch*16);
    }
    CP_COMMIT(); CP_WAIT(0);
    __syncthreads();

    uint32_t qa[16][4];
    {
        const uint32_t Qw = base + (uint32_t)(w*16*KROW)*4 + laneAQ;
#pragma unroll
        for (int k8 = 0; k8 < 16; k8++)
            LDSM_X4(qa[k8][0], qa[k8][1], qa[k8][2], qa[k8][3], Qw + k8*32);
    }
    __syncthreads();   // Q overlay region now free for K/V/P

    // ---- prologue: K(0) via cp.async, V(0) direct transpose ----
#pragma unroll
    for (int i = 0; i < 8; i++) {
        int idx = tid + i*256;
        int r = idx >> 5, ch = idx & 31;
        CP_ASYNC16(base + (uint32_t)(r*(KROW*4) + ch*16),
                   (const char*)(Kp + (size_t)r*DD) + ch*16);
    }
    CP_COMMIT();
    {
        const float* vsrc = Vp + (size_t)vkey*DD + vdg*32;
        float* vt0 = sa + OFF_V;
#pragma unroll
        for (int it = 0; it < 8; it++) {
            float4 v = *reinterpret_cast<const float4*>(vsrc + it*4);
            int d4 = vdg*32 + it*4;
            vt0[(d4+0)*VROW + vkey] = v.x;
            vt0[(d4+1)*VROW + vkey] = v.y;
            vt0[(d4+2)*VROW + vkey] = v.z;
            vt0[(d4+3)*VROW + vkey] = v.w;
        }
    }
    CP_WAIT(0);
    __syncthreads();

    float o[16][4];
#pragma unroll
    for (int df = 0; df < 16; df++)
#pragma unroll
        for (int r = 0; r < 4; r++) o[df][r] = 0.f;
    float m0r = -1e30f, m1r = -1e30f, l0r = 0.f, l1r = 0.f;

    const int nk = 2*(qt + 1);
    float* Pw = sa + OFF_P + w*16*VROW;
    const uint32_t PwA = base + (uint32_t)(OFF_P + w*16*VROW)*4;

    for (int kt = 0; kt < nk; kt++) {
        const int k0 = kt * BC;

        // prefetch next V tile into registers (consumed after softmax)
        float4 vr[8];
        if (kt + 1 < nk) {
            const float* vsrc = Vp + (size_t)(k0 + BC + vkey)*DD + vdg*32;
#pragma unroll
            for (int it = 0; it < 8; it++)
                vr[it] = *reinterpret_cast<const float4*>(vsrc + it*4);
        }

        // ---- S = Q K^T  (8 n-frags over 64 keys) ----
        float s[8][4];
#pragma unroll
        for (int nf = 0; nf < 8; nf++)
#pragma unroll
            for (int r = 0; r < 4; r++) s[nf][r] = 0.f;

#pragma unroll
        for (int k8 = 0; k8 < 16; k8++) {
            const uint32_t kb = k8*32;
            uint32_t kf[4][4];
#pragma unroll
            for (int p = 0; p < 4; p++)
                LDSM_X4(kf[p][0], kf[p][1], kf[p][2], kf[p][3],
                        base + (uint32_t)(p*16*KROW)*4 + kb + laneBK);
#pragma unroll
            for (int p = 0; p < 4; p++) {
                mma_tf32(s[2*p+0], qa[k8], &kf[p][0]);
                mma_tf32(s[2*p+1], qa[k8], &kf[p][2]);
            }
        }

        // ---- causal mask ----
        if (k0 + BC - 1 > q0 + w*16) {
            const int r0 = q0 + w*16 + g, r1 = r0 + 8;
#pragma unroll
            for (int nf = 0; nf < 8; nf++) {
                const int c0 = k0 + nf*8 + t*2, c1 = c0 + 1;
                if (c0 > r0) s[nf][0] = -1e30f;
                if (c1 > r0) s[nf][1] = -1e30f;
                if (c0 > r1) s[nf][2] = -1e30f;
                if (c1 > r1) s[nf][3] = -1e30f;
            }
        }

        __syncthreads();   // all warps done reading Ks -> safe to refill

        // kick off next K tile load (hidden behind softmax + PV)
        if (kt + 1 < nk) {
#pragma unroll
            for (int i = 0; i < 8; i++) {
                int idx = tid + i*256;
                int r = idx >> 5, ch = idx & 31;
                CP_ASYNC16(base + (uint32_t)(r*(KROW*4) + ch*16),
                           (const char*)(Kp + (size_t)(k0 + BC + r)*DD) + ch*16);
            }
        }
        CP_COMMIT();

        // ---- online softmax: row g ----
        {
            float mt = fmaxf(s[0][0], s[0][1]);
#pragma unroll
            for (int nf = 1; nf < 8; nf++)
                mt = fmaxf(mt, fmaxf(s[nf][0], s[nf][1]));
            mt = fmaxf(mt, __shfl_xor_sync(0xffffffffu, mt, 1));
            mt = fmaxf(mt, __shfl_xor_sync(0xffffffffu, mt, 2));
            float mn = fmaxf(m0r, mt);
            float corr = __expf(m0r - mn);
            m0r = mn;
            float ps = 0.f;
#pragma unroll
            for (int nf = 0; nf < 8; nf++) {
                s[nf][0] = __expf(s[nf][0] - mn); ps += s[nf][0];
                s[nf][1] = __expf(s[nf][1] - mn); ps += s[nf][1];
            }
            ps += __shfl_xor_sync(0xffffffffu, ps, 1);
            ps += __shfl_xor_sync(0xffffffffu, ps, 2);
            l0r = l0r*corr + ps;
#pragma unroll
            for (int df = 0; df < 16; df++) { o[df][0] *= corr; o[df][1] *= corr; }
#pragma unroll
            for (int nf = 0; nf < 8; nf++) {
                float2 p = { tf32r(s[nf][0]), tf32r(s[nf][1]) };
                *reinterpret_cast<float2*>(Pw + g*VROW + nf*8 + t*2) = p;
            }
        }
        // ---- row g+8 ----
        {
            float mt = fmaxf(s[0][2], s[0][3]);
#pragma unroll
            for (int nf = 1; nf < 8; nf++)
                mt = fmaxf(mt, fmaxf(s[nf][2], s[nf][3]));
            mt = fmaxf(mt, __shfl_xor_sync(0xffffffffu, mt, 1));
            mt = fmaxf(mt, __shfl_xor_sync(0xffffffffu, mt, 2));
            float mn = fmaxf(m1r, mt);
            float corr = __expf(m1r - mn);
            m1r = mn;
            float ps = 0.f;
#pragma unroll
            for (int nf = 0; nf < 8; nf++) {
                s[nf][2] = __expf(s[nf][2] - mn); ps += s[nf][2];
                s[nf][3] = __expf(s[nf][3] - mn); ps += s[nf][3];
            }
            ps += __shfl_xor_sync(0xffffffffu, ps, 1);
            ps += __shfl_xor_sync(0xffffffffu, ps, 2);
            l1r = l1r*corr + ps;
#pragma unroll
            for (int df = 0; df < 16; df++) { o[df][2] *= corr; o[df][3] *= corr; }
#pragma unroll
            for (int nf = 0; nf < 8; nf++) {
                float2 p = { tf32r(s[nf][2]), tf32r(s[nf][3]) };
                *reinterpret_cast<float2*>(Pw + (g+8)*VROW + nf*8 + t*2) = p;
            }
        }
        __syncwarp();   // P is warp-private

        // ---- store prefetched V into the other buffer ----
        if (kt + 1 < nk) {
            float* vt = sa + OFF_V + ((kt+1) & 1)*128*VROW;
#pragma unroll
            for (int it = 0; it < 8; it++) {
                int d4 = vdg*32 + it*4;
                vt[(d4+0)*VROW + vkey] = vr[it].x;
                vt[(d4+1)*VROW + vkey] = vr[it].y;
                vt[(d4+2)*VROW + vkey] = vr[it].z;
                vt[(d4+3)*VROW + vkey] = vr[it].w;
            }
        }

        // ---- O += P V  (from current V buffer) ----
        const uint32_t VtA = base + (uint32_t)(OFF_V + (kt & 1)*128*VROW)*4;
#pragma unroll
        for (int j8 = 0; j8 < 8; j8++) {
            const uint32_t jb = j8*32;
            uint32_t pa[4];
            LDSM_X4(pa[0], pa[1], pa[2], pa[3], PwA + jb + laneAP);
#pragma unroll
            for (int dp = 0; dp < 8; dp++) {
                uint32_t vb[4];
                LDSM_X4(vb[0], vb[1], vb[2], vb[3],
                        VtA + (uint32_t)(dp*16*VROW)*4 + jb + laneBV);
                mma_tf32(o[2*dp+0], pa, &vb[0]);
                mma_tf32(o[2*dp+1], pa, &vb[2]);
            }
        }

        CP_WAIT(0);
        __syncthreads();   // next K tile ready; V STS visible
    }

    // ---- normalize + store ----
    const float inv0 = 1.f / l0r, inv1 = 1.f / l1r;
    float* Op = O + ((size_t)(b*SS + q0 + w*16))*EE + h*DD;
#pragma unroll
    for (int df = 0; df < 16; df++) {
        const int col = df*8 + t*2;
        float2 v0 = { o[df][0]*inv0, o[df][1]*inv0 };
        float2 v1 = { o[df][2]*inv1, o[df][3]*inv1 };
        *reinterpret_cast<float2*>(Op + (size_t)(g    )*EE + col) = v0;
        *reinterpret_cast<float2*>(Op + (size_t)(g + 8)*EE + col) = v1;
    }
}

// ---------------------------------------------------------------------------
// kernel_launch
// ---------------------------------------------------------------------------
extern "C" void kernel_launch(void* const* d_in, const int* in_sizes, int n_in,
                              void* d_out, int out_size)
{
    const float* input = (const float*)d_in[0];
    const float* kv    = (const float*)d_in[1];
    const float* Wq    = (const float*)d_in[2];
    const float* bq    = (const float*)d_in[3];
    const float* Wk    = (const float*)d_in[4];
    const float* bk    = (const float*)d_in[5];
    const float* Wv    = (const float*)d_in[6];
    const float* bv    = (const float*)d_in[7];
    const float* Wo    = (const float*)d_in[8];
    const float* bo    = (const float*)d_in[9];
    float* out = (float*)d_out;

    float *gq, *gk, *gv, *gc;
    cudaGetSymbolAddress((void**)&gq, g_Q);
    cudaGetSymbolAddress((void**)&gk, g_K);
    cudaGetSymbolAddress((void**)&gv, g_V);
    cudaGetSymbolAddress((void**)&gc, g_C);

    cudaFuncSetAttribute(gemm_round,
                         cudaFuncAttributeMaxDynamicSharedMemorySize, SMEM_G4);
    cudaFuncSetAttribute(gemm_plain,
                         cudaFuncAttributeMaxDynamicSharedMemorySize, SMEM_G4);
    cudaFuncSetAttribute(gemm_kv,
                         cudaFuncAttributeMaxDynamicSharedMemorySize, SMEM_G2);
    cudaFuncSetAttribute(mqa_attn_tc,
                         cudaFuncAttributeMaxDynamicSharedMemorySize, SMEM_ATTN);

    // Q projection: pre-scaled + tf32-rounded output
    {
        dim3 grid(EE/128, MM/128);
        gemm_round<<<grid, 256, SMEM_G4>>>(input, Wq, bq, gq, MM, EE, EE,
                                           ATT_SCALE);
    }
    // fused K+V projections (tf32-rounded outputs)
    {
        dim3 grid(2, MM/64);
        gemm_kv<<<grid, 256, SMEM_G2>>>(kv, Wk, bk, gk, Wv, bv, gv);
    }
    // attention
    {
        dim3 grid(SS/128, HH, BB);
        mqa_attn_tc<<<grid, 256, SMEM_ATTN>>>(gq, gk, gv, gc);
    }
    // output projection into d_out
    {
        dim3 grid(EE/128, MM/128);
        gemm_plain<<<grid, 256, SMEM_G4>>>(gc, Wo, bo, out, MM, EE, EE);
    }
}

// round 10
// speedup vs baseline: 2.8263x; 1.9039x over previous
#include <cuda_runtime.h>
#include <cuda_fp16.h>
#include <cstdint>
#include <math.h>

// Problem constants
#define BB 2
#define SS 2048
#define EE 2048
#define HH 16
#define DD 128
#define MM (BB*SS)   // 4096

#define ATT_SCALE 0.08838834764831845f   // 1/sqrt(128)

// ---------------------------------------------------------------------------
// Scratch (alloc-free: __device__ globals) — fp16 pipeline
// ---------------------------------------------------------------------------
__device__ __half g_Qh [(size_t)MM * EE];  // Q proj, pre-scaled fp16
__device__ __half g_Kh [(size_t)MM * DD];
__device__ __half g_Vh [(size_t)MM * DD];
__device__ __half g_Ch [(size_t)MM * EE];  // attention out fp16
__device__ __half g_Xh [(size_t)MM * EE];  // input fp16
__device__ __half g_XKh[(size_t)MM * EE];  // kv fp16
__device__ __half g_Wqh[(size_t)EE * EE];
__device__ __half g_Wkh[(size_t)DD * EE];
__device__ __half g_Wvh[(size_t)DD * EE];
__device__ __half g_Woh[(size_t)EE * EE];

// ---------------------------------------------------------------------------
// PTX helpers (base-target-safe)
// ---------------------------------------------------------------------------
__device__ __forceinline__ uint32_t smem_u32(const void* p) {
    uint32_t a;
    asm("{ .reg .u64 t; cvta.to.shared.u64 t, %1; cvt.u32.u64 %0, t; }"
        : "=r"(a) : "l"(p));
    return a;
}

#define CP_ASYNC16(dst, src) \
    asm volatile("cp.async.cg.shared.global [%0], [%1], 16;" \
                 :: "r"(dst), "l"(src) : "memory")
#define CP_COMMIT() asm volatile("cp.async.commit_group;" ::: "memory")
#define CP_WAIT(n)  asm volatile("cp.async.wait_group %0;" :: "n"(n) : "memory")

#define LDSM_X4(r0, r1, r2, r3, addr) \
    asm volatile("ldmatrix.sync.aligned.m8n8.x4.shared.b16 {%0,%1,%2,%3}, [%4];" \
                 : "=r"(r0), "=r"(r1), "=r"(r2), "=r"(r3) : "r"(addr))
#define LDSM_X4_T(r0, r1, r2, r3, addr) \
    asm volatile("ldmatrix.sync.aligned.m8n8.x4.trans.shared.b16 {%0,%1,%2,%3}, [%4];" \
                 : "=r"(r0), "=r"(r1), "=r"(r2), "=r"(r3) : "r"(addr))

// m16n8k16 fp16 MMA, fp32 accum, D==C in-place
__device__ __forceinline__ void mma_f16(float d[4], const uint32_t a[4],
                                        const uint32_t b[2]) {
    asm volatile(
        "mma.sync.aligned.m16n8k16.row.col.f32.f16.f16.f32 "
        "{%0,%1,%2,%3}, {%4,%5,%6,%7}, {%8,%9}, {%0,%1,%2,%3};"
        : "+f"(d[0]), "+f"(d[1]), "+f"(d[2]), "+f"(d[3])
        : "r"(a[0]), "r"(a[1]), "r"(a[2]), "r"(a[3]),
          "r"(b[0]), "r"(b[1]));
}

// ---------------------------------------------------------------------------
// fp32 -> fp16 conversion pass
// ---------------------------------------------------------------------------
__global__ void __launch_bounds__(256)
cvt_h(const float* __restrict__ in, __half* __restrict__ out, int n4)
{
    int i = blockIdx.x * 256 + threadIdx.x;
    if (i < n4) {
        float4 v = reinterpret_cast<const float4*>(in)[i];
        __half2* o = reinterpret_cast<__half2*>(out) + 2*i;
        o[0] = __floats2half2_rn(v.x, v.y);
        o[1] = __floats2half2_rn(v.z, v.w);
    }
}

// ---------------------------------------------------------------------------
// fp16 GEMM: C[M,N] = A[M,K] @ B[N,K]^T + bias[N]  (CTA tile BMx128, k32/stage)
// 8 warps (2m x 4n), warp tile (16*MFRAG) x 32. 4-stage cp.async.
// smem row = 32 halves data + pad = 80 bytes.
// ---------------------------------------------------------------------------
#define GROWB 80

template<int MFRAG, bool HOUT>
__device__ __forceinline__ void gemm_body_h(
    const __half* __restrict__ A, const __half* __restrict__ Bw,
    const float* __restrict__ bias, void* Cv,
    int M, int N, int K, float scale, int m0, int n0, char* sg)
{
    constexpr int BM     = 32*MFRAG;
    constexpr int TILE_A = BM*GROWB;
    constexpr int TILE_B = 128*GROWB;
    constexpr int STAGE  = TILE_A + TILE_B;

    const uint32_t smem_base = smem_u32(sg);
    const int tid = threadIdx.x;
    const int wid = tid >> 5, lane = tid & 31;
    const int g = lane >> 2, t = lane & 3;
    const int wm = wid >> 2, wn = wid & 3;
    const int m0w = wm * 16 * MFRAG, n0w = wn * 32;

    const char* Ab = (const char*)(A  + (size_t)m0 * K);
    const char* Bb = (const char*)(Bw + (size_t)n0 * K);
    const size_t rowKB = (size_t)K * 2;
    const int NK = K / 32;

    auto stage_load = [&](int kt, int buf) {
        uint32_t sA = smem_base + (uint32_t)(buf*STAGE);
        uint32_t sB = sA + TILE_A;
        const char* gA = Ab + (size_t)kt * 64;
        const char* gB = Bb + (size_t)kt * 64;
#pragma unroll
        for (int i = 0; i < MFRAG/2; i++) {
            int idx = tid + i*256;
            int row = idx >> 2, ch = idx & 3;
            CP_ASYNC16(sA + (uint32_t)row*GROWB + ch*16,
                       gA + (size_t)row*rowKB + ch*16);
        }
#pragma unroll
        for (int i = 0; i < 2; i++) {
            int idx = tid + i*256;
            int row = idx >> 2, ch = idx & 3;
            CP_ASYNC16(sB + (uint32_t)row*GROWB + ch*16,
                       gB + (size_t)row*rowKB + ch*16);
        }
    };

    stage_load(0, 0); CP_COMMIT();
    stage_load(1, 1); CP_COMMIT();
    stage_load(2, 2); CP_COMMIT();

    const uint32_t laneA = (uint32_t)((lane & 15)*GROWB + (lane >> 4)*16);
    const uint32_t laneB = (uint32_t)(((lane & 7) + ((lane >> 4) & 1)*8)*GROWB
                                      + ((lane >> 3) & 1)*16);

    float acc[MFRAG][4][4];
#pragma unroll
    for (int mf = 0; mf < MFRAG; mf++)
#pragma unroll
        for (int nf = 0; nf < 4; nf++)
#pragma unroll
            for (int r = 0; r < 4; r++) acc[mf][nf][r] = 0.f;

    for (int kt = 0; kt < NK; kt++) {
        CP_WAIT(2);
        __syncthreads();
        if (kt + 3 < NK) stage_load(kt + 3, (kt + 3) & 3);
        CP_COMMIT();

        const uint32_t As = smem_base + (uint32_t)((kt & 3)*STAGE);
        const uint32_t Bs = As + TILE_A;
        const uint32_t Aw = As + (uint32_t)(m0w*GROWB) + laneA;
        const uint32_t Bw2 = Bs + (uint32_t)(n0w*GROWB) + laneB;

#pragma unroll
        for (int k16 = 0; k16 < 2; k16++) {
            const uint32_t kb = k16*32;
            uint32_t a[MFRAG][4];
#pragma unroll
            for (int mf = 0; mf < MFRAG; mf++)
                LDSM_X4(a[mf][0], a[mf][1], a[mf][2], a[mf][3],
                        Aw + (uint32_t)(mf*16*GROWB) + kb);
            uint32_t b[2][4];
#pragma unroll
            for (int p = 0; p < 2; p++)
                LDSM_X4(b[p][0], b[p][1], b[p][2], b[p][3],
                        Bw2 + (uint32_t)(p*16*GROWB) + kb);
#pragma unroll
            for (int mf = 0; mf < MFRAG; mf++)
#pragma unroll
                for (int p = 0; p < 2; p++) {
                    mma_f16(acc[mf][2*p+0], a[mf], &b[p][0]);
                    mma_f16(acc[mf][2*p+1], a[mf], &b[p][2]);
                }
        }
    }

#pragma unroll
    for (int mf = 0; mf < MFRAG; mf++) {
        const int r0 = m0 + m0w + mf*16 + g;
#pragma unroll
        for (int nf = 0; nf < 4; nf++) {
            const int col = n0 + n0w + nf*8 + t*2;
            float2 bb = *reinterpret_cast<const float2*>(bias + col);
            float x0 = acc[mf][nf][0] + bb.x, y0 = acc[mf][nf][1] + bb.y;
            float x1 = acc[mf][nf][2] + bb.x, y1 = acc[mf][nf][3] + bb.y;
            if (HOUT) {
                __half* C = (__half*)Cv;
                *reinterpret_cast<__half2*>(C + (size_t)r0*N + col) =
                    __floats2half2_rn(x0*scale, y0*scale);
                *reinterpret_cast<__half2*>(C + (size_t)(r0+8)*N + col) =
                    __floats2half2_rn(x1*scale, y1*scale);
            } else {
                float* C = (float*)Cv;
                *reinterpret_cast<float2*>(C + (size_t)r0*N + col) =
                    make_float2(x0, y0);
                *reinterpret_cast<float2*>(C + (size_t)(r0+8)*N + col) =
                    make_float2(x1, y1);
            }
        }
    }
}

#define SMEM_GH4 (4*(128+128)*GROWB)   // 81920
#define SMEM_GH2 (4*(64+128)*GROWB)    // 61440

__global__ void __launch_bounds__(256, 2)
gemm_h_qproj(const __half* __restrict__ A, const __half* __restrict__ Bw,
             const float* __restrict__ bias, __half* __restrict__ C,
             int M, int N, int K, float scale)
{
    extern __shared__ char sg[];
    gemm_body_h<4, true>(A, Bw, bias, C, M, N, K, scale,
                         blockIdx.y*128, blockIdx.x*128, sg);
}

__global__ void __launch_bounds__(256, 2)
gemm_h_fp32(const __half* __restrict__ A, const __half* __restrict__ Bw,
            const float* __restrict__ bias, float* __restrict__ C,
            int M, int N, int K)
{
    extern __shared__ char sg[];
    gemm_body_h<4, false>(A, Bw, bias, C, M, N, K, 1.f,
                          blockIdx.y*128, blockIdx.x*128, sg);
}

__global__ void __launch_bounds__(256, 2)
gemm_h_kv(const __half* __restrict__ kvIn,
          const __half* __restrict__ Wk, const float* __restrict__ bk,
          __half* __restrict__ gK,
          const __half* __restrict__ Wv, const float* __restrict__ bv,
          __half* __restrict__ gV)
{
    extern __shared__ char sg[];
    const bool isV = (blockIdx.x != 0);
    gemm_body_h<2, true>(kvIn, isV ? Wv : Wk, isV ? bv : bk,
                         isV ? gV : gK, MM, DD, EE, 1.f,
                         blockIdx.y*64, 0, sg);
}

// ---------------------------------------------------------------------------
// fp16 causal MQA flash attention
// Br=128 (8 warps x m16), Bc=64. grid (S/128, H, B), block 256.
// K single-buffered + V double-buffered via cp.async; Q in registers.
// smem (halves): K[64][136] | V[2][64][136] | P[8][16][72]  (Q overlays K+V)
// ---------------------------------------------------------------------------
#define BC 64
#define KRB 272              // K/V row bytes (136 halves)
#define PRB 144              // P row bytes (72 halves)
#define OFFV_H 8704
#define OFFP_H 26112
#define SMEM_ATTN ((OFFP_H + 8*16*72)*2)   // 70656 bytes

__global__ void __launch_bounds__(256)
mqa_attn_h(const __half* __restrict__ Q, const __half* __restrict__ Kb,
           const __half* __restrict__ Vb, __half* __restrict__ O)
{
    extern __shared__ __align__(16) __half sp[];
    const uint32_t base = smem_u32(sp);

    const int qt = (int)gridDim.x - 1 - (int)blockIdx.x;  // longest first
    const int h = blockIdx.y, b = blockIdx.z;
    const int q0 = qt * 128;
    const int tid = threadIdx.x;
    const int w = tid >> 5, lane = tid & 31;
    const int g = lane >> 2, t = lane & 3;

    const __half* Qp = Q  + ((size_t)(b*SS + q0))*EE + h*DD;
    const __half* Kp = Kb + (size_t)b*SS*DD;
    const __half* Vp = Vb + (size_t)b*SS*DD;

    const uint32_t laneAQ = (uint32_t)((lane & 15)*KRB + (lane >> 4)*16);
    const uint32_t laneBK = (uint32_t)(((lane & 7) + ((lane >> 4) & 1)*8)*KRB
                                       + ((lane >> 3) & 1)*16);
    const uint32_t laneAP = (uint32_t)((lane & 15)*PRB + (lane >> 4)*16);
    const uint32_t laneBV = (uint32_t)(((lane & 7) + ((lane >> 3) & 1)*8)*KRB
                                       + ((lane >> 4) & 1)*16);

    // ---- prologue: Q tile -> smem overlay -> registers ----
#pragma unroll
    for (int i = 0; i < 8; i++) {
        int idx = tid + i*256;
        int r = idx >> 4, ch = idx & 15;
        CP_ASYNC16(base + (uint32_t)(r*KRB + ch*16),
                   (const char*)Qp + (size_t)r*(EE*2) + ch*16);
    }
    CP_COMMIT(); CP_WAIT(0);
    __syncthreads();

    uint32_t qa[8][4];
    {
        const uint32_t Qw = base + (uint32_t)(w*16*KRB) + laneAQ;
#pragma unroll
        for (int k16 = 0; k16 < 8; k16++)
            LDSM_X4(qa[k16][0], qa[k16][1], qa[k16][2], qa[k16][3],
                    Qw + k16*32);
    }
    __syncthreads();   // overlay free for K/V

    // ---- prologue: K(0), V(0) ----
#pragma unroll
    for (int i = 0; i < 4; i++) {
        int idx = tid + i*256;
        int r = idx >> 4, ch = idx & 15;
        CP_ASYNC16(base + (uint32_t)(r*KRB + ch*16),
                   (const char*)Kp + (size_t)r*(DD*2) + ch*16);
        CP_ASYNC16(base + (uint32_t)(OFFV_H*2 + r*KRB + ch*16),
                   (const char*)Vp + (size_t)r*(DD*2) + ch*16);
    }
    CP_COMMIT(); CP_WAIT(0);
    __syncthreads();

    float o[16][4];
#pragma unroll
    for (int df = 0; df < 16; df++)
#pragma unroll
        for (int r = 0; r < 4; r++) o[df][r] = 0.f;
    float m0r = -1e30f, m1r = -1e30f, l0r = 0.f, l1r = 0.f;

    const int nk = 2*(qt + 1);
    __half* Pw = sp + OFFP_H + w*16*72;
    const uint32_t PwA = base + (uint32_t)(OFFP_H*2 + w*16*PRB);

    for (int kt = 0; kt < nk; kt++) {
        const int k0 = kt * BC;

        // ---- S = Q K^T ----
        float s[8][4];
#pragma unroll
        for (int nf = 0; nf < 8; nf++)
#pragma unroll
            for (int r = 0; r < 4; r++) s[nf][r] = 0.f;

#pragma unroll
        for (int k16 = 0; k16 < 8; k16++) {
            const uint32_t kb = k16*32;
            uint32_t kf[4][4];
#pragma unroll
            for (int p = 0; p < 4; p++)
                LDSM_X4(kf[p][0], kf[p][1], kf[p][2], kf[p][3],
                        base + (uint32_t)(p*16*KRB) + kb + laneBK);
#pragma unroll
            for (int p = 0; p < 4; p++) {
                mma_f16(s[2*p+0], qa[k16], &kf[p][0]);
                mma_f16(s[2*p+1], qa[k16], &kf[p][2]);
            }
        }

        // ---- causal mask ----
        if (k0 + BC - 1 > q0 + w*16) {
            const int r0 = q0 + w*16 + g, r1 = r0 + 8;
#pragma unroll
            for (int nf = 0; nf < 8; nf++) {
                const int c0 = k0 + nf*8 + t*2, c1 = c0 + 1;
                if (c0 > r0) s[nf][0] = -1e30f;
                if (c1 > r0) s[nf][1] = -1e30f;
                if (c0 > r1) s[nf][2] = -1e30f;
                if (c1 > r1) s[nf][3] = -1e30f;
            }
        }

        __syncthreads();   // all warps done reading K tile

        // kick off next K + V tiles (hidden behind softmax + PV)
        if (kt + 1 < nk) {
            const uint32_t vdst = (uint32_t)(OFFV_H*2 + ((kt+1) & 1)*(64*KRB));
#pragma unroll
            for (int i = 0; i < 4; i++) {
                int idx = tid + i*256;
                int r = idx >> 4, ch = idx & 15;
                CP_ASYNC16(base + (uint32_t)(r*KRB + ch*16),
                           (const char*)Kp + (size_t)(k0+BC+r)*(DD*2) + ch*16);
                CP_ASYNC16(base + vdst + (uint32_t)(r*KRB + ch*16),
                           (const char*)Vp + (size_t)(k0+BC+r)*(DD*2) + ch*16);
            }
        }
        CP_COMMIT();

        // ---- online softmax: row g ----
        {
            float mt = fmaxf(s[0][0], s[0][1]);
#pragma unroll
            for (int nf = 1; nf < 8; nf++)
                mt = fmaxf(mt, fmaxf(s[nf][0], s[nf][1]));
            mt = fmaxf(mt, __shfl_xor_sync(0xffffffffu, mt, 1));
            mt = fmaxf(mt, __shfl_xor_sync(0xffffffffu, mt, 2));
            float mn = fmaxf(m0r, mt);
            float corr = __expf(m0r - mn);
            m0r = mn;
            float ps = 0.f;
#pragma unroll
            for (int nf = 0; nf < 8; nf++) {
                s[nf][0] = __expf(s[nf][0] - mn); ps += s[nf][0];
                s[nf][1] = __expf(s[nf][1] - mn); ps += s[nf][1];
            }
            ps += __shfl_xor_sync(0xffffffffu, ps, 1);
            ps += __shfl_xor_sync(0xffffffffu, ps, 2);
            l0r = l0r*corr + ps;
#pragma unroll
            for (int df = 0; df < 16; df++) { o[df][0] *= corr; o[df][1] *= corr; }
#pragma unroll
            for (int nf = 0; nf < 8; nf++)
                *reinterpret_cast<__half2*>(Pw + g*72 + nf*8 + t*2) =
                    __floats2half2_rn(s[nf][0], s[nf][1]);
        }
        // ---- row g+8 ----
        {
            float mt = fmaxf(s[0][2], s[0][3]);
#pragma unroll
            for (int nf = 1; nf < 8; nf++)
                mt = fmaxf(mt, fmaxf(s[nf][2], s[nf][3]));
            mt = fmaxf(mt, __shfl_xor_sync(0xffffffffu, mt, 1));
            mt = fmaxf(mt, __shfl_xor_sync(0xffffffffu, mt, 2));
            float mn = fmaxf(m1r, mt);
            float corr = __expf(m1r - mn);
            m1r = mn;
            float ps = 0.f;
#pragma unroll
            for (int nf = 0; nf < 8; nf++) {
                s[nf][2] = __expf(s[nf][2] - mn); ps += s[nf][2];
                s[nf][3] = __expf(s[nf][3] - mn); ps += s[nf][3];
            }
            ps += __shfl_xor_sync(0xffffffffu, ps, 1);
            ps += __shfl_xor_sync(0xffffffffu, ps, 2);
            l1r = l1r*corr + ps;
#pragma unroll
            for (int df = 0; df < 16; df++) { o[df][2] *= corr; o[df][3] *= corr; }
#pragma unroll
            for (int nf = 0; nf < 8; nf++)
                *reinterpret_cast<__half2*>(Pw + (g+8)*72 + nf*8 + t*2) =
                    __floats2half2_rn(s[nf][2], s[nf][3]);
        }
        __syncwarp();   // P is warp-private

        // ---- O += P V  (V row-major, B frags via ldmatrix.trans) ----
        const uint32_t VtA = base + (uint32_t)(OFFV_H*2 + (kt & 1)*(64*KRB));
#pragma unroll
        for (int j16 = 0; j16 < 4; j16++) {
            uint32_t pa[4];
            LDSM_X4(pa[0], pa[1], pa[2], pa[3], PwA + j16*32 + laneAP);
#pragma unroll
            for (int dp = 0; dp < 8; dp++) {
                uint32_t vb[4];
                LDSM_X4_T(vb[0], vb[1], vb[2], vb[3],
                          VtA + (uint32_t)(j16*16*KRB) + dp*32 + laneBV);
                mma_f16(o[2*dp+0], pa, &vb[0]);
                mma_f16(o[2*dp+1], pa, &vb[2]);
            }
        }

        CP_WAIT(0);
        __syncthreads();   // next K/V tiles ready
    }

    // ---- normalize + fp16 store ----
    const float inv0 = 1.f / l0r, inv1 = 1.f / l1r;
    __half* Op = O + ((size_t)(b*SS + q0 + w*16))*EE + h*DD;
#pragma unroll
    for (int df = 0; df < 16; df++) {
        const int col = df*8 + t*2;
        *reinterpret_cast<__half2*>(Op + (size_t)(g    )*EE + col) =
            __floats2half2_rn(o[df][0]*inv0, o[df][1]*inv0);
        *reinterpret_cast<__half2*>(Op + (size_t)(g + 8)*EE + col) =
            __floats2half2_rn(o[df][2]*inv1, o[df][3]*inv1);
    }
}

// ---------------------------------------------------------------------------
// kernel_launch
// ---------------------------------------------------------------------------
extern "C" void kernel_launch(void* const* d_in, const int* in_sizes, int n_in,
                              void* d_out, int out_size)
{
    const float* input = (const float*)d_in[0];
    const float* kv    = (const float*)d_in[1];
    const float* Wq    = (const float*)d_in[2];
    const float* bq    = (const float*)d_in[3];
    const float* Wk    = (const float*)d_in[4];
    const float* bk    = (const float*)d_in[5];
    const float* Wv    = (const float*)d_in[6];
    const float* bv    = (const float*)d_in[7];
    const float* Wo    = (const float*)d_in[8];
    const float* bo    = (const float*)d_in[9];
    float* out = (float*)d_out;

    __half *qh, *kh, *vh, *ch, *xh, *xkh, *wqh, *wkh, *wvh, *woh;
    cudaGetSymbolAddress((void**)&qh,  g_Qh);
    cudaGetSymbolAddress((void**)&kh,  g_Kh);
    cudaGetSymbolAddress((void**)&vh,  g_Vh);
    cudaGetSymbolAddress((void**)&ch,  g_Ch);
    cudaGetSymbolAddress((void**)&xh,  g_Xh);
    cudaGetSymbolAddress((void**)&xkh, g_XKh);
    cudaGetSymbolAddress((void**)&wqh, g_Wqh);
    cudaGetSymbolAddress((void**)&wkh, g_Wkh);
    cudaGetSymbolAddress((void**)&wvh, g_Wvh);
    cudaGetSymbolAddress((void**)&woh, g_Woh);

    cudaFuncSetAttribute(gemm_h_qproj,
                         cudaFuncAttributeMaxDynamicSharedMemorySize, SMEM_GH4);
    cudaFuncSetAttribute(gemm_h_fp32,
                         cudaFuncAttributeMaxDynamicSharedMemorySize, SMEM_GH4);
    cudaFuncSetAttribute(gemm_h_kv,
                         cudaFuncAttributeMaxDynamicSharedMemorySize, SMEM_GH2);
    cudaFuncSetAttribute(mqa_attn_h,
                         cudaFuncAttributeMaxDynamicSharedMemorySize, SMEM_ATTN);

    // fp32 -> fp16 conversion passes
    {
        int n4 = MM*EE/4;
        cvt_h<<<(n4+255)/256, 256>>>(input, xh,  n4);
        cvt_h<<<(n4+255)/256, 256>>>(kv,    xkh, n4);
        int w4 = EE*EE/4;
        cvt_h<<<(w4+255)/256, 256>>>(Wq, wqh, w4);
        cvt_h<<<(w4+255)/256, 256>>>(Wo, woh, w4);
        int s4 = DD*EE/4;
        cvt_h<<<(s4+255)/256, 256>>>(Wk, wkh, s4);
        cvt_h<<<(s4+255)/256, 256>>>(Wv, wvh, s4);
    }

    // Q projection: pre-scaled fp16 output
    {
        dim3 grid(EE/128, MM/128);
        gemm_h_qproj<<<grid, 256, SMEM_GH4>>>(xh, wqh, bq, qh, MM, EE, EE,
                                              ATT_SCALE);
    }
    // fused K+V projections (fp16 outputs)
    {
        dim3 grid(2, MM/64);
        gemm_h_kv<<<grid, 256, SMEM_GH2>>>(xkh, wkh, bk, kh, wvh, bv, vh);
    }
    // attention
    {
        dim3 grid(SS/128, HH, BB);
        mqa_attn_h<<<grid, 256, SMEM_ATTN>>>(qh, kh, vh, ch);
    }
    // output projection into d_out (fp32)
    {
        dim3 grid(EE/128, MM/128);
        gemm_h_fp32<<<grid, 256, SMEM_GH4>>>(ch, woh, bo, out, MM, EE, EE);
    }
}